// round 1
// baseline (speedup 1.0000x reference)
#include <cuda_runtime.h>
#include <cuda_bf16.h>

// Problem constants
#define NT   16384      // B*T tokens
#define D    2048       // hidden dim
#define NE   64         // experts
#define TOPK 8
#define TOK  64         // tokens per CTA
#define DC   64         // d-chunk per iteration
#define TPB  256
#define WROW 68         // padded smem row for w chunk (float4-aligned, bank-friendly)

// Transposed router weights: wT[d][e] = w[e][d]
__device__ float g_wT[D * NE];

__global__ void transpose_w_kernel(const float* __restrict__ w) {
    int idx = blockIdx.x * blockDim.x + threadIdx.x;   // 0 .. D*NE-1
    int d = idx >> 6;       // / NE
    int e = idx & (NE - 1);
    g_wT[idx] = w[e * D + d];   // write coalesced
}

__global__ __launch_bounds__(TPB) void gate_kernel(
    const float* __restrict__ x,
    const float* __restrict__ gate_b,
    float* __restrict__ out)
{
    // smem: ws[DC][WROW] then xs[TOK][DC]; sc[TOK][WROW] aliases ws after GEMM
    __shared__ float smem[DC * WROW + TOK * DC];
    float* ws = smem;                  // [DC][WROW]
    float* xs = smem + DC * WROW;      // [TOK][DC]
    float* sc = smem;                  // [TOK][WROW] (alias, used after GEMM)

    const int t    = threadIdx.x;
    const int tok0 = blockIdx.x * TOK;
    const int tg   = t >> 4;           // token group 0..15 (4 tokens each)
    const int eg   = t & 15;           // expert group 0..15 (4 experts each)

    float acc[4][4];
#pragma unroll
    for (int i = 0; i < 4; i++)
#pragma unroll
        for (int j = 0; j < 4; j++) acc[i][j] = 0.f;

    for (int dc = 0; dc < D; dc += DC) {
        // ---- stage x chunk: xs[tok][kk], 64x64 floats, coalesced float4 ----
#pragma unroll
        for (int i = 0; i < 4; i++) {
            int f   = t + i * TPB;          // 0..1023 (float4 units)
            int tok = f >> 4;               // 16 float4 per row
            int kv  = (f & 15) << 2;
            float4 v = *(const float4*)&x[(long)(tok0 + tok) * D + dc + kv];
            *(float4*)&xs[tok * DC + kv] = v;
        }
        // ---- stage w chunk from wT: ws[kk][e], 64x64 floats ----
#pragma unroll
        for (int i = 0; i < 4; i++) {
            int f   = t + i * TPB;
            int row = f >> 4;               // 16 float4 per row of 64
            int cv  = (f & 15) << 2;
            float4 v = *(const float4*)&g_wT[(dc + row) * NE + cv];
            *(float4*)&ws[row * WROW + cv] = v;
        }
        __syncthreads();

        // ---- 4x4 register-tile GEMM over this chunk ----
#pragma unroll 2
        for (int kk = 0; kk < DC; kk += 4) {
            float4 a[4], b[4];
#pragma unroll
            for (int i = 0; i < 4; i++)
                a[i] = *(const float4*)&xs[(tg * 4 + i) * DC + kk];
#pragma unroll
            for (int j = 0; j < 4; j++)
                b[j] = *(const float4*)&ws[(kk + j) * WROW + eg * 4];
#pragma unroll
            for (int i = 0; i < 4; i++) {
                acc[i][0] = fmaf(a[i].x, b[0].x, fmaf(a[i].y, b[1].x, fmaf(a[i].z, b[2].x, fmaf(a[i].w, b[3].x, acc[i][0]))));
                acc[i][1] = fmaf(a[i].x, b[0].y, fmaf(a[i].y, b[1].y, fmaf(a[i].z, b[2].y, fmaf(a[i].w, b[3].y, acc[i][1]))));
                acc[i][2] = fmaf(a[i].x, b[0].z, fmaf(a[i].y, b[1].z, fmaf(a[i].z, b[2].z, fmaf(a[i].w, b[3].z, acc[i][2]))));
                acc[i][3] = fmaf(a[i].x, b[0].w, fmaf(a[i].y, b[1].w, fmaf(a[i].z, b[2].w, fmaf(a[i].w, b[3].w, acc[i][3]))));
            }
        }
        __syncthreads();
    }

    // ---- sigmoid + bias; write scores (global + smem for top-k) ----
    float* scores_out = out + 2L * NT * TOPK;
    float b0 = gate_b[eg * 4 + 0];
    float b1 = gate_b[eg * 4 + 1];
    float b2 = gate_b[eg * 4 + 2];
    float b3 = gate_b[eg * 4 + 3];
#pragma unroll
    for (int i = 0; i < 4; i++) {
        int tok = tg * 4 + i;
        float4 sv;
        sv.x = 1.f / (1.f + __expf(-acc[i][0])) + b0;
        sv.y = 1.f / (1.f + __expf(-acc[i][1])) + b1;
        sv.z = 1.f / (1.f + __expf(-acc[i][2])) + b2;
        sv.w = 1.f / (1.f + __expf(-acc[i][3])) + b3;
        *(float4*)&scores_out[(long)(tok0 + tok) * NE + eg * 4] = sv;
        sc[tok * WROW + eg * 4 + 0] = sv.x;
        sc[tok * WROW + eg * 4 + 1] = sv.y;
        sc[tok * WROW + eg * 4 + 2] = sv.z;
        sc[tok * WROW + eg * 4 + 3] = sv.w;
    }
    __syncthreads();

    // ---- top-8 per token (one thread per token), first-index tie-break ----
    if (t < TOK) {
        int token = tok0 + t;
        float* row = &sc[t * WROW];
        float wk[TOPK];
        int   ik[TOPK];
        float sum = 0.f;
#pragma unroll
        for (int k = 0; k < TOPK; k++) {
            float m = -1e30f;
            int   mi = 0;
            for (int e = 0; e < NE; e++) {
                float v = row[e];
                if (v > m) { m = v; mi = e; }
            }
            row[mi] = -1e30f;
            wk[k] = m;
            ik[k] = mi;
            sum += m;
        }
        float inv = 1.f / sum;
#pragma unroll
        for (int k = 0; k < TOPK; k++) {
            out[(long)token * TOPK + k] = wk[k] * inv;
            out[(long)NT * TOPK + (long)token * TOPK + k] = (float)ik[k];
        }
    }
}

extern "C" void kernel_launch(void* const* d_in, const int* in_sizes, int n_in,
                              void* d_out, int out_size) {
    const float* x      = (const float*)d_in[0];
    const float* w      = (const float*)d_in[1];
    const float* gate_b = (const float*)d_in[2];
    float* out = (float*)d_out;

    transpose_w_kernel<<<(D * NE) / TPB, TPB>>>(w);
    gate_kernel<<<NT / TOK, TPB>>>(x, gate_b, out);
}